// round 8
// baseline (speedup 1.0000x reference)
#include <cuda_runtime.h>
#include <cuda_fp16.h>
#include <math.h>
#include <stdint.h>

#define BB 128
#define RR 4608
#define NR 8                 // r per staged batch
#define NBATCH 4
#define NRB (NR*NBATCH)      // 32 r per CTA
#define NCTA (RR/NRB)        // 144 -> one co-resident wave (<=148 SMs)
#define INV_B (1.0f/128.0f)
#define INV_R (1.0f/4608.0f)

// smem tile geometry (48-byte padded rows -> conflict-free fragment LDS)
#define XROW 48
#define XT_RL (128*XROW)     // 6144 B per rl
#define WT_RL (64*XROW)      // 3072 B per rl
#define DSM_BYTES (NR*XT_RL + NR*WT_RL)   // 73728

typedef unsigned long long ull;

// fp16 copies of inputs (written by pass0 phase while it computes)
__device__ __half g_xh[(size_t)RR * BB * 16];    // [r][b][i]
__device__ __half g_wh[(size_t)RR * 64 * 16];    // [r][ko][i]
__device__ float g_S[3][BB * 64];                // s0, S1, S2 (atomic accum)
__device__ float g_Zf[4];
__device__ float g_v[2][BB * 64];
__device__ float g_b1[RR * 2];
__device__ unsigned g_bar[8];                    // grid-barrier slots

// ---------------- f32x2 helpers ------------------------------------------
__device__ __forceinline__ ull pack2(float lo, float hi) {
    ull r; asm("mov.b64 %0, {%1, %2};" : "=l"(r) : "f"(lo), "f"(hi)); return r;
}
__device__ __forceinline__ void unpack2(ull v, float& lo, float& hi) {
    asm("mov.b64 {%0, %1}, %2;" : "=f"(lo), "=f"(hi) : "l"(v));
}
__device__ __forceinline__ ull fma2(ull a, ull b, ull c) {
    ull d; asm("fma.rn.f32x2 %0, %1, %2, %3;" : "=l"(d) : "l"(a), "l"(b), "l"(c));
    return d;
}

// ---------------- m16n8k16 f16 MMA ---------------------------------------
__device__ __forceinline__ void mma16816(float* d, const uint32_t* a,
                                         const uint32_t* b, const float* c) {
    asm volatile(
        "mma.sync.aligned.m16n8k16.row.col.f32.f16.f16.f32 "
        "{%0,%1,%2,%3}, {%4,%5,%6,%7}, {%8,%9}, {%10,%11,%12,%13};"
        : "=f"(d[0]), "=f"(d[1]), "=f"(d[2]), "=f"(d[3])
        : "r"(a[0]), "r"(a[1]), "r"(a[2]), "r"(a[3]),
          "r"(b[0]), "r"(b[1]),
          "f"(c[0]), "f"(c[1]), "f"(c[2]), "f"(c[3]));
}

__device__ __forceinline__ uint2 cvt4(float4 v) {
    __half2 lo = __float22half2_rn(make_float2(v.x, v.y));
    __half2 hi = __float22half2_rn(make_float2(v.z, v.w));
    uint2 o; o.x = *(uint32_t*)&lo; o.y = *(uint32_t*)&hi;
    return o;
}

// ---------------- grid barrier (all 144 CTAs co-resident) ------------------
__device__ __forceinline__ void grid_bar(int slot) {
    __syncthreads();
    if (threadIdx.x == 0) {
        __threadfence();
        unsigned prev = atomicAdd(&g_bar[slot], 1u);
        if (prev + 1u < (unsigned)NCTA) {
            while (*(volatile unsigned*)&g_bar[slot] < (unsigned)NCTA)
                __nanosleep(64);
        }
        __threadfence();
    }
    __syncthreads();
}

// ---------------------------------------------------------------------------
// Staging helpers
// ---------------------------------------------------------------------------
__device__ __forceinline__ void stage_conv(char* xt, char* wt,
                                           const float4* __restrict__ x4,
                                           const float4* __restrict__ w4,
                                           int r0, int t) {
    #pragma unroll
    for (int j = 0; j < 8; j++) {
        int idx = j * 512 + t;
        int rl = idx >> 9, rem = idx & 511, b = rem >> 2, q = rem & 3;
        uint2 u = cvt4(x4[((size_t)b * RR + r0 + rl) * 4 + q]);
        *(uint2*)(xt + rl * XT_RL + b * XROW + q * 8) = u;
        ((uint2*)g_xh)[((size_t)(r0 + rl) * BB + b) * 4 + q] = u;
    }
    #pragma unroll
    for (int j = 0; j < 4; j++) {
        int idx = j * 512 + t;
        int rl = idx >> 8, rem = idx & 255, ko = rem >> 2, q = rem & 3;
        uint2 u = cvt4(w4[((size_t)(r0 + rl) * 64 + ko) * 4 + q]);
        *(uint2*)(wt + rl * WT_RL + ko * XROW + q * 8) = u;
        ((uint2*)g_wh)[((size_t)(r0 + rl) * 64 + ko) * 4 + q] = u;
    }
}

__device__ __forceinline__ void stage_tiles(char* xt, char* wt, int r0, int t) {
    #pragma unroll
    for (int j = 0; j < 8; j++) {
        int idx = j * 512 + t;
        int rl = idx >> 9, rem = idx & 511, b = rem >> 2, q = rem & 3;
        uint2 v = ((const uint2*)g_xh)[((size_t)(r0 + rl) * BB + b) * 4 + q];
        *(uint2*)(xt + rl * XT_RL + b * XROW + q * 8) = v;
    }
    #pragma unroll
    for (int j = 0; j < 4; j++) {
        int idx = j * 512 + t;
        int rl = idx >> 8, rem = idx & 255, ko = rem >> 2, q = rem & 3;
        uint2 v = ((const uint2*)g_wh)[((size_t)(r0 + rl) * 64 + ko) * 4 + q];
        *(uint2*)(wt + rl * WT_RL + ko * XROW + q * 8) = v;
    }
}

__device__ __forceinline__ void load_a(const char* xb, uint32_t* A) {
    A[0] = *(const uint32_t*)(xb);
    A[1] = *(const uint32_t*)(xb + 8 * XROW);
    A[2] = *(const uint32_t*)(xb + 16);
    A[3] = *(const uint32_t*)(xb + 8 * XROW + 16);
}

// ---------------------------------------------------------------------------
// Phase: pass0 (+input conversion). C accumulates over 32 r; epilogue REDG.
// ---------------------------------------------------------------------------
__device__ void pass0_phase(char* xt, char* wt,
                            const float4* __restrict__ x4,
                            const float4* __restrict__ w4) {
    const int t = threadIdx.x, lane = t & 31, w = t >> 5;
    const int m = w & 7, kh = w >> 3;
    const int gp = lane >> 2, tig = lane & 3;
    const int xoff = (m * 16 + gp) * XROW + tig * 4;
    const int woff = (kh * 32 + gp) * XROW + tig * 4;

    float CF[4][4];
    #pragma unroll
    for (int nt = 0; nt < 4; nt++)
        #pragma unroll
        for (int c = 0; c < 4; c++) CF[nt][c] = 0.f;

    const int rc = blockIdx.x * NRB;
    for (int bt = 0; bt < NBATCH; bt++) {
        if (bt) __syncthreads();
        stage_conv(xt, wt, x4, w4, rc + bt * NR, t);
        __syncthreads();
        #pragma unroll
        for (int rl = 0; rl < NR; rl++) {
            uint32_t A[4];
            load_a(xt + rl * XT_RL + xoff, A);
            const char* wb = wt + rl * WT_RL + woff;
            #pragma unroll
            for (int nt = 0; nt < 4; nt++) {
                uint32_t Bf[2];
                Bf[0] = *(const uint32_t*)(wb + nt * 8 * XROW);
                Bf[1] = *(const uint32_t*)(wb + nt * 8 * XROW + 16);
                mma16816(CF[nt], A, Bf, CF[nt]);
            }
        }
    }
    float* dst = g_S[0];
    #pragma unroll
    for (int nt = 0; nt < 4; nt++) {
        const int ko = kh * 32 + nt * 8 + 2 * tig;
        const int b0 = m * 16 + gp;
        atomicAdd(&dst[b0 * 64 + ko],           CF[nt][0]);
        atomicAdd(&dst[b0 * 64 + ko + 1],       CF[nt][1]);
        atomicAdd(&dst[(b0 + 8) * 64 + ko],     CF[nt][2]);
        atomicAdd(&dst[(b0 + 8) * 64 + ko + 1], CF[nt][3]);
    }
}

// ---------------------------------------------------------------------------
// Phase: routing (deferred softmax), retained C fragments, mini-batch of 4.
// ---------------------------------------------------------------------------
__device__ void routing_phase(char* xt, char* wt, int pass,
                              float (*red)[2][128], float* ebc) {
    const int t = threadIdx.x, lane = t & 31, w = t >> 5;
    const int m = w & 7, kh = w >> 3;
    const int gp = lane >> 2, tig = lane & 3;
    const int xoff = (m * 16 + gp) * XROW + tig * 4;
    const int woff = (kh * 32 + gp) * XROW + tig * 4;

    ull v2[2][4];
    {
        const float* vp = g_v[pass];
        #pragma unroll
        for (int row = 0; row < 2; row++) {
            const int b = m * 16 + gp + row * 8;
            #pragma unroll
            for (int nt = 0; nt < 4; nt++) {
                float2 q = *(const float2*)&vp[b * 64 + kh * 32 + nt * 8 + 2 * tig];
                v2[row][nt] = pack2(q.x, q.y);
            }
        }
    }
    ull S2[2][4];
    #pragma unroll
    for (int row = 0; row < 2; row++)
        #pragma unroll
        for (int nt = 0; nt < 4; nt++) S2[row][nt] = 0ull;
    float zacc = 0.f;

    const int rc = blockIdx.x * NRB;
    for (int bt = 0; bt < NBATCH; bt++) {
        const int r0 = rc + bt * NR;
        stage_tiles(xt, wt, r0, t);
        __syncthreads();

        #pragma unroll
        for (int mini = 0; mini < 2; mini++) {
            float CF[4][4][4];

            #pragma unroll
            for (int rlm = 0; rlm < 4; rlm++) {
                const int rl = mini * 4 + rlm;
                uint32_t A[4];
                load_a(xt + rl * XT_RL + xoff, A);
                const char* wb = wt + rl * WT_RL + woff;
                ull d0 = 0ull, d1 = 0ull;
                #pragma unroll
                for (int nt = 0; nt < 4; nt++) {
                    uint32_t Bf[2];
                    Bf[0] = *(const uint32_t*)(wb + nt * 8 * XROW);
                    Bf[1] = *(const uint32_t*)(wb + nt * 8 * XROW + 16);
                    float* C = CF[rlm][nt];
                    C[0] = 0.f; C[1] = 0.f; C[2] = 0.f; C[3] = 0.f;
                    mma16816(C, A, Bf, C);
                    d0 = fma2(pack2(C[0], C[1]), v2[0][nt], d0);
                    d1 = fma2(pack2(C[2], C[3]), v2[1][nt], d1);
                }
                float l0, h0, l1, h1;
                unpack2(d0, l0, h0); unpack2(d1, l1, h1);
                float dr0 = l0 + h0, dr1 = l1 + h1;
                dr0 += __shfl_xor_sync(0xffffffffu, dr0, 1);
                dr0 += __shfl_xor_sync(0xffffffffu, dr0, 2);
                dr1 += __shfl_xor_sync(0xffffffffu, dr1, 1);
                dr1 += __shfl_xor_sync(0xffffffffu, dr1, 2);
                if (tig == 0) {
                    red[rlm][kh][m * 16 + gp]     = dr0;
                    red[rlm][kh][m * 16 + gp + 8] = dr1;
                }
            }
            __syncthreads();

            if (w < 8) {
                const int rlm = w >> 1, kk = w & 1;
                const float* rrow = red[rlm][kk];
                float s = rrow[lane] + rrow[lane + 32] +
                          rrow[lane + 64] + rrow[lane + 96];
                #pragma unroll
                for (int sh = 16; sh >= 1; sh >>= 1)
                    s += __shfl_xor_sync(0xffffffffu, s, sh);
                if (lane == 0) {
                    float bn = s * INV_B;
                    const int gi = (r0 + mini * 4 + rlm) * 2 + kk;
                    if (pass) bn += g_b1[gi];
                    else      g_b1[gi] = bn;
                    float e = expf(bn);
                    ebc[rlm * 2 + kk] = e;
                    zacc += e;
                }
            }
            __syncthreads();

            #pragma unroll
            for (int rlm = 0; rlm < 4; rlm++) {
                const float e = ebc[rlm * 2 + kh];
                const ull e2 = pack2(e, e);
                #pragma unroll
                for (int nt = 0; nt < 4; nt++) {
                    const float* C = CF[rlm][nt];
                    S2[0][nt] = fma2(pack2(C[0], C[1]), e2, S2[0][nt]);
                    S2[1][nt] = fma2(pack2(C[2], C[3]), e2, S2[1][nt]);
                }
            }
        }
    }

    float* dst = g_S[pass + 1];
    #pragma unroll
    for (int nt = 0; nt < 4; nt++) {
        const int ko = kh * 32 + nt * 8 + 2 * tig;
        const int b0 = m * 16 + gp;
        float lo, hi;
        unpack2(S2[0][nt], lo, hi);
        atomicAdd(&dst[b0 * 64 + ko], lo);
        atomicAdd(&dst[b0 * 64 + ko + 1], hi);
        unpack2(S2[1][nt], lo, hi);
        atomicAdd(&dst[(b0 + 8) * 64 + ko], lo);
        atomicAdd(&dst[(b0 + 8) * 64 + ko + 1], hi);
    }
    if (w < 8 && lane == 0) atomicAdd(&g_Zf[pass * 2 + (w & 1)], zacc);
}

// ---------------------------------------------------------------------------
// Phase: squash on CTAs 0..15 (one warp per capsule, 256 capsules total).
// ---------------------------------------------------------------------------
__device__ void squash_phase(int mode, float* __restrict__ out) {
    if (blockIdx.x >= 16) return;
    const int t = threadIdx.x, lane = t & 31, w = t >> 5;
    const int cap = blockIdx.x * 16 + w;      // 0..255 = b*2+k
    const int k = cap & 1;
    const int base = cap * 32 + lane;
    float s = g_S[mode][base];
    if (mode == 0) s *= INV_R;
    else           s /= g_Zf[(mode - 1) * 2 + k];
    float sq = s * s;
    #pragma unroll
    for (int m = 16; m >= 1; m >>= 1) sq += __shfl_xor_sync(0xffffffffu, sq, m);
    const float sn = sq;
    const float f = sqrtf(sn) / (0.5f + sn);
    const float v = s * f;
    if (mode == 2) out[base] = v;
    else           g_v[mode][base] = v;
}

// ---------------------------------------------------------------------------
__global__ void zero_kernel() {
    int t = blockIdx.x * blockDim.x + threadIdx.x;   // 8192
    g_S[0][t] = 0.f;
    g_S[1][t] = 0.f;
    g_S[2][t] = 0.f;
    if (t < 4) g_Zf[t] = 0.f;
    if (t < 8) g_bar[t] = 0u;
}

__global__ __launch_bounds__(512, 1) void mega_kernel(const float4* __restrict__ x4,
                                                      const float4* __restrict__ w4,
                                                      float* __restrict__ out) {
    extern __shared__ char dsm[];
    char* xt = dsm;
    char* wt = dsm + NR * XT_RL;
    __shared__ float red[4][2][128];
    __shared__ float ebc[8];

    pass0_phase(xt, wt, x4, w4);
    grid_bar(0);
    squash_phase(0, out);
    grid_bar(1);
    routing_phase(xt, wt, 0, red, ebc);
    grid_bar(2);
    squash_phase(1, out);
    grid_bar(3);
    routing_phase(xt, wt, 1, red, ebc);
    grid_bar(4);
    squash_phase(2, out);
}

// ---------------------------------------------------------------------------
extern "C" void kernel_launch(void* const* d_in, const int* in_sizes, int n_in,
                              void* d_out, int out_size) {
    const float* x = (const float*)d_in[0];   // [128, 4608, 16]
    const float* W = (const float*)d_in[1];   // [1, 4608, 2, 32, 16]
    float* out = (float*)d_out;               // [128, 2, 32]

    cudaFuncSetAttribute(mega_kernel,
                         cudaFuncAttributeMaxDynamicSharedMemorySize, DSM_BYTES);

    zero_kernel<<<16, 512>>>();
    mega_kernel<<<NCTA, 512, DSM_BYTES>>>((const float4*)x, (const float4*)W, out);
}